// round 15
// baseline (speedup 1.0000x reference)
#include <cuda_runtime.h>
#include <cuda_bf16.h>

// ConvTreeBlock: N=1e6 nodes, C=16, KS=9.
// R15 = R10 (proven, 366us) with ONE change: 4 nodes per thread (A/B/C/D at
// base+{0,128,256,384}) so each weight LDS.128 feeds 4 nodes' FMAs.
// LDS wavefronts + loop/shfl/issue per node-j ~halved again. Pair-gather,
// shfl.xor(1) exchange, f32x2, fused stats, BN1-in-gather all unchanged.
// Launches: zero_stats -> conv1(+stats1) -> conv2(BN1+leaky inline, +stats2) -> bnact2.

#define NMAX 1000000

__device__ float g_y1[(size_t)NMAX * 16];   // conv1 raw output (device-side only!)
__device__ float g_stats[64];               // [0:16]sum1 [16:32]ssq1 [32:48]sum2 [48:64]ssq2

static constexpr float EPS   = 1e-5f;
static constexpr float SLOPE = 0.2f;

// ---- f32x2 helpers (exact fp32 semantics, 2 MACs/instr) ----
__device__ __forceinline__ unsigned long long pack2(float lo, float hi) {
    unsigned long long r;
    asm("mov.b64 %0, {%1, %2};" : "=l"(r) : "f"(lo), "f"(hi));
    return r;
}
__device__ __forceinline__ unsigned long long dup2(float x) {
    unsigned long long r;
    asm("mov.b64 %0, {%1, %1};" : "=l"(r) : "f"(x));
    return r;
}
__device__ __forceinline__ void fma2(unsigned long long& acc, unsigned long long a, unsigned long long b) {
    asm("fma.rn.f32x2 %0, %1, %2, %0;" : "+l"(acc) : "l"(a), "l"(b));
}
__device__ __forceinline__ void unpack2(unsigned long long v, float& lo, float& hi) {
    asm("mov.b64 {%0, %1}, %2;" : "=f"(lo), "=f"(hi) : "l"(v));
}

__global__ void k_zero_stats()
{
    if (threadIdx.x < 64) g_stats[threadIdx.x] = 0.0f;
}

#define NODES_PER_THREAD 4

// Block = 256 threads = 512 nodes (4 per thread, pair-cooperative).
// Thread pair (2*nl, 2*nl+1): thread p loads row-half [8p,8p+8) for its 4
// nodes (8x LDG.128/j, pair shares 128B lines), exchanges halves via
// shfl.xor(1), computes output channels [8p,8p+8) for 4 nodes as 4x4 packed
// f32x2 accumulators. One weight LDS.128 serves 4 nodes.
template<int LAYER>
__global__ __launch_bounds__(256, 1)
void k_conv(const float* __restrict__ src_param,  // LAYER1: data
            const int*   __restrict__ ind,
            const float* __restrict__ w,          // [c][o][j] : c*144 + o*9 + j
            const float* __restrict__ bias,       // LAYER1 only
            const float* __restrict__ gamma,      // LAYER2: gamma1
            const float* __restrict__ beta,       // LAYER2: beta1
            float*       __restrict__ dst_param,  // LAYER2: d_out
            int n, int stat_off_in, int stat_off_out)
{
    // device-side scratch selection (NEVER pass __device__ symbols from host)
    const float* src = (LAYER == 1) ? src_param : (const float*)g_y1;
    float*       dst = (LAYER == 1) ? (float*)g_y1 : dst_param;

    __shared__ __align__(16) float ws[2304];   // ws[j*256 + c*16 + o]
    __shared__ float s_ab[32];                 // a[16], b[16] (LAYER 2)
    __shared__ float s_stat[32];               // sum[16], ssq[16]

    const int tid = threadIdx.x;

    for (int s = tid; s < 2304; s += 256) {
        int o = s & 15, c = (s >> 4) & 15, j = s >> 8;
        ws[s] = w[c * 144 + o * 9 + j];
    }
    if (tid < 32) s_stat[tid] = 0.0f;
    if (LAYER == 2 && tid < 16) {
        float inv  = 1.0f / (float)n;
        float mean = g_stats[stat_off_in + tid] * inv;
        float var  = g_stats[stat_off_in + 16 + tid] * inv - mean * mean;
        float a    = gamma[tid] * rsqrtf(var + EPS);
        s_ab[tid]      = a;
        s_ab[16 + tid] = beta[tid] - a * mean;
    }
    __syncthreads();

    const int nl = tid >> 1;                   // pair index 0..127
    const int p  = tid & 1;                    // half: channels [8p, 8p+8)

    int   nodeN[NODES_PER_THREAD];
    bool  actN [NODES_PER_THREAD];
    int   ibase[NODES_PER_THREAD];
#pragma unroll
    for (int m = 0; m < NODES_PER_THREAD; ++m) {
        nodeN[m] = blockIdx.x * (128 * NODES_PER_THREAD) + m * 128 + nl;
        actN[m]  = nodeN[m] < n;
        ibase[m] = actN[m] ? nodeN[m] * 9 : 0;
    }

    unsigned long long acc[NODES_PER_THREAD][4];
#pragma unroll
    for (int k = 0; k < 4; ++k) {
        unsigned long long b0 = (LAYER == 1)
            ? pack2(__ldg(bias + p * 8 + 2 * k), __ldg(bias + p * 8 + 2 * k + 1))
            : pack2(0.0f, 0.0f);
#pragma unroll
        for (int m = 0; m < NODES_PER_THREAD; ++m) acc[m][k] = b0;
    }

    // per-thread weight views (runtime p offset into SHARED mem; broadcast pair)
    const float* w_own = ws + (p * 8) * 16 + p * 8;        // own-half input channels
    const float* w_oth = ws + ((1 - p) * 8) * 16 + p * 8;  // partner-half input channels

    // software pipeline: prefetch all nodes' row-halves for j+1 while computing j
    float4 c0[NODES_PER_THREAD], c1[NODES_PER_THREAD];
#pragma unroll
    for (int m = 0; m < NODES_PER_THREAD; ++m) {
        int r = ind[ibase[m]];
        const float* rp = src + (size_t)r * 16 + p * 8;
        c0[m] = *reinterpret_cast<const float4*>(rp);
        c1[m] = *reinterpret_cast<const float4*>(rp + 4);
    }

#pragma unroll 1   // body fits I$ L0/L1.5; within-warp pipeline hides L2 latency
    for (int j = 0; j < 9; ++j) {
        float4 n0[NODES_PER_THREAD], n1[NODES_PER_THREAD];
        if (j < 8) {
#pragma unroll
            for (int m = 0; m < NODES_PER_THREAD; ++m) {
                int r = ind[ibase[m] + j + 1];
                const float* rp = src + (size_t)r * 16 + p * 8;
                n0[m] = *reinterpret_cast<const float4*>(rp);
                n1[m] = *reinterpret_cast<const float4*>(rp + 4);
            }
        } else {
#pragma unroll
            for (int m = 0; m < NODES_PER_THREAD; ++m) {
                n0[m] = make_float4(0.f, 0.f, 0.f, 0.f);
                n1[m] = n0[m];
            }
        }

        float own[NODES_PER_THREAD][8];
#pragma unroll
        for (int m = 0; m < NODES_PER_THREAD; ++m) {
            own[m][0] = c0[m].x; own[m][1] = c0[m].y; own[m][2] = c0[m].z; own[m][3] = c0[m].w;
            own[m][4] = c1[m].x; own[m][5] = c1[m].y; own[m][6] = c1[m].z; own[m][7] = c1[m].w;
        }
        if (LAYER == 2) {
#pragma unroll
            for (int k = 0; k < 8; ++k) {
                float a = s_ab[p * 8 + k], b = s_ab[16 + p * 8 + k];
#pragma unroll
                for (int m = 0; m < NODES_PER_THREAD; ++m) {
                    float v = fmaf(own[m][k], a, b);
                    own[m][k] = fmaxf(v, SLOPE * v);
                }
            }
        }
        float oth[NODES_PER_THREAD][8];
#pragma unroll
        for (int m = 0; m < NODES_PER_THREAD; ++m)
#pragma unroll
            for (int k = 0; k < 8; ++k)
                oth[m][k] = __shfl_xor_sync(0xFFFFFFFFu, own[m][k], 1);

        const float* wj_own = w_own + j * 256;
        const float* wj_oth = w_oth + j * 256;
#pragma unroll
        for (int k = 0; k < 8; ++k) {          // input channel p*8+k : 1 weight fetch, 4 nodes
            ulonglong2 w01 = *reinterpret_cast<const ulonglong2*>(wj_own + k * 16);
            ulonglong2 w23 = *reinterpret_cast<const ulonglong2*>(wj_own + k * 16 + 4);
#pragma unroll
            for (int m = 0; m < NODES_PER_THREAD; ++m) {
                unsigned long long x = dup2(own[m][k]);
                fma2(acc[m][0], x, w01.x);
                fma2(acc[m][1], x, w01.y);
                fma2(acc[m][2], x, w23.x);
                fma2(acc[m][3], x, w23.y);
            }
        }
#pragma unroll
        for (int k = 0; k < 8; ++k) {          // input channel (1-p)*8+k
            ulonglong2 w01 = *reinterpret_cast<const ulonglong2*>(wj_oth + k * 16);
            ulonglong2 w23 = *reinterpret_cast<const ulonglong2*>(wj_oth + k * 16 + 4);
#pragma unroll
            for (int m = 0; m < NODES_PER_THREAD; ++m) {
                unsigned long long x = dup2(oth[m][k]);
                fma2(acc[m][0], x, w01.x);
                fma2(acc[m][1], x, w01.y);
                fma2(acc[m][2], x, w23.x);
                fma2(acc[m][3], x, w23.y);
            }
        }
#pragma unroll
        for (int m = 0; m < NODES_PER_THREAD; ++m) { c0[m] = n0[m]; c1[m] = n1[m]; }
    }

    // ---- epilogue: store + fused stats ----
    float sv[8] = {0, 0, 0, 0, 0, 0, 0, 0};
    float qv[8] = {0, 0, 0, 0, 0, 0, 0, 0};
#pragma unroll
    for (int m = 0; m < NODES_PER_THREAD; ++m) {
        float av[8];
#pragma unroll
        for (int k = 0; k < 4; ++k) unpack2(acc[m][k], av[2 * k], av[2 * k + 1]);
        if (actN[m]) {
            float4* o4 = reinterpret_cast<float4*>(dst + (size_t)nodeN[m] * 16 + p * 8);
            o4[0] = make_float4(av[0], av[1], av[2], av[3]);
            o4[1] = make_float4(av[4], av[5], av[6], av[7]);
            // fold into stats only when active
#pragma unroll
            for (int k = 0; k < 8; ++k) { sv[k] += av[k]; qv[k] += av[k] * av[k]; }
        }
    }
#pragma unroll
    for (int d = 2; d < 32; d <<= 1) {
#pragma unroll
        for (int k = 0; k < 8; ++k) {
            sv[k] += __shfl_xor_sync(0xFFFFFFFFu, sv[k], d);
            qv[k] += __shfl_xor_sync(0xFFFFFFFFu, qv[k], d);
        }
    }
    if ((tid & 31) < 2) {    // lane0: p=0 (ch0..7), lane1: p=1 (ch8..15)
#pragma unroll
        for (int k = 0; k < 8; ++k) {
            atomicAdd(&s_stat[p * 8 + k],      sv[k]);
            atomicAdd(&s_stat[16 + p * 8 + k], qv[k]);
        }
    }
    __syncthreads();
    if (tid < 32) atomicAdd(&g_stats[stat_off_out + tid], s_stat[tid]);
}

// Final: out = leaky(a2[c]*y2 + b2[c] + data), in place on d_out.
__global__ __launch_bounds__(256)
void k_bnact2(const float* __restrict__ gamma,
              const float* __restrict__ beta,
              const float* __restrict__ res,
              float*       __restrict__ out,
              int n, int off)
{
    __shared__ float sa[16], sb[16];
    if (threadIdx.x < 16) {
        int c = threadIdx.x;
        float inv  = 1.0f / (float)n;
        float mean = g_stats[off + c] * inv;
        float var  = g_stats[off + 16 + c] * inv - mean * mean;
        float a    = gamma[c] * rsqrtf(var + EPS);
        sa[c] = a;
        sb[c] = beta[c] - a * mean;
    }
    __syncthreads();

    int n4 = n * 4;
    int stride = gridDim.x * 256;
    for (int i = blockIdx.x * 256 + threadIdx.x; i < n4; i += stride) {
        float4 v = reinterpret_cast<float4*>(out)[i];
        float4 r = reinterpret_cast<const float4*>(res)[i];
        int c0 = (i & 3) * 4;
        v.x = fmaf(v.x, sa[c0 + 0], sb[c0 + 0]) + r.x;  v.x = fmaxf(v.x, SLOPE * v.x);
        v.y = fmaf(v.y, sa[c0 + 1], sb[c0 + 1]) + r.y;  v.y = fmaxf(v.y, SLOPE * v.y);
        v.z = fmaf(v.z, sa[c0 + 2], sb[c0 + 2]) + r.z;  v.z = fmaxf(v.z, SLOPE * v.z);
        v.w = fmaf(v.w, sa[c0 + 3], sb[c0 + 3]) + r.w;  v.w = fmaxf(v.w, SLOPE * v.w);
        reinterpret_cast<float4*>(out)[i] = v;
    }
}

extern "C" void kernel_launch(void* const* d_in, const int* in_sizes, int n_in,
                              void* d_out, int out_size)
{
    const float* data   = (const float*)d_in[0];
    const int*   ind    = (const int*)  d_in[1];
    const float* w1     = (const float*)d_in[2];
    const float* b1     = (const float*)d_in[3];
    const float* gamma1 = (const float*)d_in[4];
    const float* beta1  = (const float*)d_in[5];
    const float* w2     = (const float*)d_in[6];
    const float* gamma2 = (const float*)d_in[7];
    const float* beta2  = (const float*)d_in[8];
    float*       out    = (float*)d_out;

    int n = in_sizes[0] / 16;
    if (n > NMAX) n = NMAX;

    int nodes_per_block = 128 * NODES_PER_THREAD;   // 512
    int conv_blocks = (n + nodes_per_block - 1) / nodes_per_block;
    int ew_blocks   = 1184;

    k_zero_stats<<<1, 64>>>();
    k_conv<1><<<conv_blocks, 256>>>(data, ind, w1, b1, nullptr, nullptr, nullptr, n, 0, 0);
    k_conv<2><<<conv_blocks, 256>>>(nullptr, ind, w2, nullptr, gamma1, beta1, out, n, 0, 32);
    k_bnact2<<<ew_blocks, 256>>>(gamma2, beta2, data, out, n, 32);
}